// round 1
// baseline (speedup 1.0000x reference)
#include <cuda_runtime.h>

#define BSZ 8
#define SEQ 1024
#define DIM 512
#define NHEAD 8
#define HDIM 64
#define NTOK (BSZ*SEQ)                 // 8192
#define NELEM ((size_t)NTOK*DIM)       // 4194304

// Intermediate scratch (static device globals; no allocations).
__device__ float g_q[NELEM];
__device__ float g_k[NELEM];
__device__ float g_v[NELEM];
__device__ float g_att[NELEM];
__device__ float g_ln0[NELEM];
__device__ float g_mid[NELEM];

// ---------------------------------------------------------------------------
// Generic 128x128x16 fp32 tiled GEMM body.  C[M,512] = A[M,512] @ W[512,512].
// MODE 0: C = acc + bias
// MODE 1: C = resid + relu(acc + bias)
// ---------------------------------------------------------------------------
template <int MODE>
__device__ __forceinline__ void gemm_body(const float* __restrict__ A,
                                          const float* __restrict__ W,
                                          const float* __restrict__ bias,
                                          const float* __restrict__ resid,
                                          float* __restrict__ C)
{
    const int K = DIM, N = DIM;
    __shared__ float As[16][128];
    __shared__ float Bs[16][128];

    const int row0 = blockIdx.y * 128;
    const int col0 = blockIdx.x * 128;
    const int tid  = threadIdx.x;          // 0..255
    const int tx   = tid & 15;
    const int ty   = tid >> 4;

    float c[8][8];
#pragma unroll
    for (int i = 0; i < 8; i++)
#pragma unroll
        for (int j = 0; j < 8; j++) c[i][j] = 0.f;

    for (int kk = 0; kk < K; kk += 16) {
        // A tile 128x16, stored transposed into As[k][m]
#pragma unroll
        for (int it = 0; it < 2; it++) {
            int fid = tid + it * 256;          // 0..511
            int r   = fid >> 2;
            int kq  = (fid & 3) * 4;
            float4 a = *(const float4*)(A + (size_t)(row0 + r) * K + kk + kq);
            As[kq + 0][r] = a.x;
            As[kq + 1][r] = a.y;
            As[kq + 2][r] = a.z;
            As[kq + 3][r] = a.w;
        }
        // B tile 16x128, natural layout
#pragma unroll
        for (int it = 0; it < 2; it++) {
            int fid = tid + it * 256;
            int kr  = fid >> 5;
            int cq  = fid & 31;
            *(((float4*)&Bs[kr][0]) + cq) =
                *(const float4*)(W + (size_t)(kk + kr) * N + col0 + cq * 4);
        }
        __syncthreads();

#pragma unroll
        for (int k = 0; k < 16; k++) {
            float4 a0 = *(((float4*)&As[k][0]) + ty);
            float4 a1 = *(((float4*)&As[k][0]) + ty + 16);
            float4 b0 = *(((float4*)&Bs[k][0]) + tx);
            float4 b1 = *(((float4*)&Bs[k][0]) + tx + 16);
            float av[8] = {a0.x, a0.y, a0.z, a0.w, a1.x, a1.y, a1.z, a1.w};
            float bv[8] = {b0.x, b0.y, b0.z, b0.w, b1.x, b1.y, b1.z, b1.w};
#pragma unroll
            for (int i = 0; i < 8; i++)
#pragma unroll
                for (int j = 0; j < 8; j++) c[i][j] += av[i] * bv[j];
        }
        __syncthreads();
    }

    // Epilogue
#pragma unroll
    for (int i = 0; i < 8; i++) {
        int grow = row0 + ((i < 4) ? (ty * 4 + i) : (ty * 4 + 64 + i - 4));
#pragma unroll
        for (int jh = 0; jh < 2; jh++) {
            int gcol = col0 + tx * 4 + jh * 64;
            float4 o;
            o.x = c[i][jh * 4 + 0] + bias[gcol + 0];
            o.y = c[i][jh * 4 + 1] + bias[gcol + 1];
            o.z = c[i][jh * 4 + 2] + bias[gcol + 2];
            o.w = c[i][jh * 4 + 3] + bias[gcol + 3];
            size_t gi = (size_t)grow * N + gcol;
            if (MODE == 1) {
                float4 r = *(const float4*)(resid + gi);
                o.x = r.x + fmaxf(o.x, 0.f);
                o.y = r.y + fmaxf(o.y, 0.f);
                o.z = r.z + fmaxf(o.z, 0.f);
                o.w = r.w + fmaxf(o.w, 0.f);
            }
            *(float4*)(C + gi) = o;
        }
    }
}

// Fused Q/K/V projections: blockIdx.z selects which projection.
__global__ __launch_bounds__(256)
void qkv_gemm(const float* __restrict__ queries, const float* __restrict__ keys,
              const float* __restrict__ Wq, const float* __restrict__ bq,
              const float* __restrict__ Wk, const float* __restrict__ bk,
              const float* __restrict__ Wv, const float* __restrict__ bv)
{
    const float* A; const float* W; const float* bias; float* C;
    if (blockIdx.z == 0)      { A = queries; W = Wq; bias = bq; C = g_q; }
    else if (blockIdx.z == 1) { A = keys;    W = Wk; bias = bk; C = g_k; }
    else                      { A = keys;    W = Wv; bias = bv; C = g_v; }
    gemm_body<0>(A, W, bias, nullptr, C);
}

// Output projection with fused residual + relu.
__global__ __launch_bounds__(256)
void o_gemm(const float* __restrict__ Wo, const float* __restrict__ bo)
{
    gemm_body<1>(g_ln0, Wo, bo, g_ln0, g_mid);
}

// ---------------------------------------------------------------------------
// Flash attention: one thread per (b,h,sq) row.  d=64 kept in registers.
// o = qh + softmax(mask(qh kh^T / sqrt(512))) @ vh
// ---------------------------------------------------------------------------
__global__ __launch_bounds__(128)
void attn_kernel(const float* __restrict__ pres_q, const float* __restrict__ pres_k)
{
    const int bh = blockIdx.y;            // 0..63
    const int b  = bh >> 3;
    const int h  = bh & 7;
    const int sq = blockIdx.x * 128 + threadIdx.x;

    const float* qrow = g_q + ((size_t)b * SEQ + sq) * DIM + h * HDIM;
    float4 qv[16];
#pragma unroll
    for (int i = 0; i < 16; i++) qv[i] = ((const float4*)qrow)[i];

    const float presq   = pres_q[b * SEQ + sq];
    const float INFC    = 1e38f;
    const float rs      = 0.04419417382415922f;   // 1/sqrt(512)

    float4 acc[16];
#pragma unroll
    for (int i = 0; i < 16; i++) acc[i] = make_float4(0.f, 0.f, 0.f, 0.f);
    float m = -1e38f, l = 0.f;

    __shared__ float4 Ks[16][16];
    __shared__ float4 Vs[16][16];
    __shared__ float  pks[16];

    for (int t = 0; t < SEQ / 16; t++) {
        int k0 = t * 16;
        __syncthreads();
        {
            int fid = threadIdx.x;
#pragma unroll
            for (int it = 0; it < 2; it++, fid += 128) {
                int j = fid >> 4, i = fid & 15;
                size_t gidx = ((size_t)b * SEQ + k0 + j) * DIM + h * HDIM;
                Ks[j][i] = ((const float4*)(g_k + gidx))[i];
                Vs[j][i] = ((const float4*)(g_v + gidx))[i];
            }
            if (threadIdx.x < 16) pks[threadIdx.x] = pres_k[b * SEQ + k0 + threadIdx.x];
        }
        __syncthreads();

        float s[16];
#pragma unroll
        for (int j = 0; j < 16; j++) {
            float sum = 0.f;
#pragma unroll
            for (int i = 0; i < 16; i++) {
                float4 kv = Ks[j][i];
                sum += qv[i].x * kv.x + qv[i].y * kv.y + qv[i].z * kv.z + qv[i].w * kv.w;
            }
            // exact reference masking order
            float l1  = presq * (sum * rs) - (1.f - presq) * INFC;
            float pkj = pks[j];
            s[j] = pkj * l1 - (1.f - pkj) * INFC;
        }

        float tm = s[0];
#pragma unroll
        for (int j = 1; j < 16; j++) tm = fmaxf(tm, s[j]);
        float mnew = fmaxf(m, tm);
        float fac  = __expf(m - mnew);
        m = mnew;
        l *= fac;
#pragma unroll
        for (int i = 0; i < 16; i++) {
            acc[i].x *= fac; acc[i].y *= fac; acc[i].z *= fac; acc[i].w *= fac;
        }
#pragma unroll
        for (int j = 0; j < 16; j++) {
            float p = __expf(s[j] - m);
            l += p;
#pragma unroll
            for (int i = 0; i < 16; i++) {
                float4 vvv = Vs[j][i];
                acc[i].x += p * vvv.x;
                acc[i].y += p * vvv.y;
                acc[i].z += p * vvv.z;
                acc[i].w += p * vvv.w;
            }
        }
    }

    float inv = 1.f / l;
    float* orow = g_att + ((size_t)b * SEQ + sq) * DIM + h * HDIM;
#pragma unroll
    for (int i = 0; i < 16; i++) {
        float4 o;
        o.x = qv[i].x + acc[i].x * inv;
        o.y = qv[i].y + acc[i].y * inv;
        o.z = qv[i].z + acc[i].z * inv;
        o.w = qv[i].w + acc[i].w * inv;
        ((float4*)orow)[i] = o;
    }
}

// ---------------------------------------------------------------------------
// LayerNorm over last dim (512).  One block per row, 128 threads.
// ---------------------------------------------------------------------------
__device__ __forceinline__ void ln_body(const float* __restrict__ in,
                                        float* __restrict__ out,
                                        const float* __restrict__ g,
                                        const float* __restrict__ b)
{
    const int row = blockIdx.x;
    const int tid = threadIdx.x;
    const float* x = in + (size_t)row * DIM;

    float v[4];
#pragma unroll
    for (int i = 0; i < 4; i++) v[i] = x[tid + i * 128];

    float s = v[0] + v[1] + v[2] + v[3];
#pragma unroll
    for (int o = 16; o > 0; o >>= 1) s += __shfl_xor_sync(0xffffffffu, s, o);
    __shared__ float red1[4];
    __shared__ float red2[4];
    int wid = tid >> 5;
    if ((tid & 31) == 0) red1[wid] = s;
    __syncthreads();
    float mu = (red1[0] + red1[1] + red1[2] + red1[3]) * (1.f / DIM);

    float q = 0.f;
#pragma unroll
    for (int i = 0; i < 4; i++) { float d = v[i] - mu; q += d * d; }
#pragma unroll
    for (int o = 16; o > 0; o >>= 1) q += __shfl_xor_sync(0xffffffffu, q, o);
    if ((tid & 31) == 0) red2[wid] = q;
    __syncthreads();
    float var  = (red2[0] + red2[1] + red2[2] + red2[3]) * (1.f / DIM);
    float rstd = rsqrtf(var + 1e-5f);

#pragma unroll
    for (int i = 0; i < 4; i++) {
        int c = tid + i * 128;
        out[(size_t)row * DIM + c] = (v[i] - mu) * rstd * g[c] + b[c];
    }
}

__global__ __launch_bounds__(128)
void ln0_kernel(const float* __restrict__ g0, const float* __restrict__ b0)
{
    ln_body(g_att, g_ln0, g0, b0);
}

__global__ __launch_bounds__(128)
void ln1_kernel(const float* __restrict__ g1, const float* __restrict__ b1,
                float* __restrict__ out)
{
    ln_body(g_mid, out, g1, b1);
}

// ---------------------------------------------------------------------------
extern "C" void kernel_launch(void* const* d_in, const int* in_sizes, int n_in,
                              void* d_out, int out_size)
{
    const float* queries = (const float*)d_in[0];
    const float* keys    = (const float*)d_in[1];
    const float* pq      = (const float*)d_in[2];
    const float* pk      = (const float*)d_in[3];

    // num_heads may or may not be materialized as a scalar input at index 4.
    int base = 4;
    if (n_in >= 5 && in_sizes[4] == 1) base = 5;

    const float* Wq = (const float*)d_in[base + 0];
    const float* bq = (const float*)d_in[base + 1];
    const float* Wk = (const float*)d_in[base + 2];
    const float* bk = (const float*)d_in[base + 3];
    const float* Wv = (const float*)d_in[base + 4];
    const float* bv = (const float*)d_in[base + 5];
    const float* Wo = (const float*)d_in[base + 6];
    const float* bo = (const float*)d_in[base + 7];
    const float* g0 = (const float*)d_in[base + 8];
    const float* b0 = (const float*)d_in[base + 9];
    const float* g1 = (const float*)d_in[base + 10];
    const float* b1 = (const float*)d_in[base + 11];
    float* out = (float*)d_out;

    // 1) Q/K/V projections
    qkv_gemm<<<dim3(DIM / 128, NTOK / 128, 3), 256>>>(queries, keys,
                                                      Wq, bq, Wk, bk, Wv, bv);
    // 2) attention (+ residual q)
    attn_kernel<<<dim3(SEQ / 128, BSZ * NHEAD), 128>>>(pq, pk);
    // 3) LayerNorm 0
    ln0_kernel<<<NTOK, 128>>>(g0, b0);
    // 4) output projection + residual + relu
    o_gemm<<<dim3(DIM / 128, NTOK / 128), 256>>>(Wo, bo);
    // 5) LayerNorm 1 -> d_out
    ln1_kernel<<<NTOK, 128>>>(g1, b1, out);
}